// round 3
// baseline (speedup 1.0000x reference)
#include <cuda_runtime.h>

// ROIAlign, torchvision semantics (matches the JAX reference):
//   features: (N=2, C=256, H=200, W=304) fp32, NCHW
//   boxes:    (R=1000, 5) fp32  [batch_idx, x1, y1, x2, y2] in image coords
//   output:   (R, C, 7, 7) fp32
// spatial_scale = 0.25, sampling_ratio = 2, mean over the 2x2 sample grid.

namespace {

constexpr int   C_DIM  = 256;
constexpr int   H_DIM  = 200;
constexpr int   W_DIM  = 304;
constexpr int   PH     = 7;
constexpr int   PW     = 7;
constexpr int   G      = 2;      // sampling_ratio
constexpr float SCALE  = 0.25f;

// torchvision bilinear_interpolate clamping along one axis.
__device__ __forceinline__ void axis_interp(float coord, int size,
                                            int& lo, int& hi,
                                            float& frac, bool& valid) {
    valid = (coord >= -1.0f) && (coord <= (float)size);
    float c = fmaxf(coord, 0.0f);
    int low = (int)c;                 // floor (c >= 0)
    if (low >= size - 1) {
        lo = size - 1; hi = size - 1; frac = 0.0f;
    } else {
        lo = low; hi = low + 1; frac = c - (float)low;
    }
}

__global__ void roi_align_kernel(const float* __restrict__ feat,
                                 const float* __restrict__ boxes,
                                 float* __restrict__ out,
                                 int total) {
    int idx = blockIdx.x * blockDim.x + threadIdx.x;
    if (idx >= total) return;

    // pw fastest -> warp covers spatial bins of one (box, channel) plane:
    // coalesced output writes, spatially-clustered feature gathers.
    int pw = idx % PW;
    int ph = (idx / PW) % PH;
    int c  = (idx / (PW * PH)) % C_DIM;
    int r  = idx / (PW * PH * C_DIM);

    const float* bx = boxes + (size_t)r * 5;
    int   b  = (int)__ldg(bx + 0);
    float x1 = __ldg(bx + 1) * SCALE;
    float y1 = __ldg(bx + 2) * SCALE;
    float x2 = __ldg(bx + 3) * SCALE;
    float y2 = __ldg(bx + 4) * SCALE;

    float roi_w = fmaxf(x2 - x1, 1.0f);
    float roi_h = fmaxf(y2 - y1, 1.0f);
    float bin_w = roi_w * (1.0f / PW);
    float bin_h = roi_h * (1.0f / PH);

    const float* fp = feat + ((size_t)b * C_DIM + c) * (H_DIM * W_DIM);

    // Per-axis sample interpolation params (shared across the 2x2 grid).
    int   yl[G], yh[G], xl[G], xh[G];
    float fy[G], fx[G];
    bool  vy[G], vx[G];
#pragma unroll
    for (int i = 0; i < G; i++) {
        float off = ((float)i + 0.5f) * (1.0f / G);
        float y = y1 + ((float)ph + off) * bin_h;
        float x = x1 + ((float)pw + off) * bin_w;
        axis_interp(y, H_DIM, yl[i], yh[i], fy[i], vy[i]);
        axis_interp(x, W_DIM, xl[i], xh[i], fx[i], vx[i]);
    }

    float acc = 0.0f;
#pragma unroll
    for (int iy = 0; iy < G; iy++) {
        if (!vy[iy]) continue;
        float ly = fy[iy], hy = 1.0f - ly;
        const float* rowl = fp + yl[iy] * W_DIM;
        const float* rowh = fp + yh[iy] * W_DIM;
#pragma unroll
        for (int ix = 0; ix < G; ix++) {
            if (!vx[ix]) continue;
            float lx = fx[ix], hx = 1.0f - lx;
            float vll = __ldg(rowl + xl[ix]);
            float vlh = __ldg(rowl + xh[ix]);
            float vhl = __ldg(rowh + xl[ix]);
            float vhh = __ldg(rowh + xh[ix]);
            acc += hy * (hx * vll + lx * vlh) + ly * (hx * vhl + lx * vhh);
        }
    }

    out[idx] = acc * (1.0f / (G * G));
}

} // namespace

extern "C" void kernel_launch(void* const* d_in, const int* in_sizes, int n_in,
                              void* d_out, int out_size) {
    const float* features = (const float*)d_in[0];
    const float* boxes    = (const float*)d_in[1];
    float*       out      = (float*)d_out;

    int total = out_size;            // R * C * PH * PW
    int threads = 256;
    int blocks = (total + threads - 1) / threads;
    roi_align_kernel<<<blocks, threads>>>(features, boxes, out, total);
}

// round 4
// speedup vs baseline: 1.2733x; 1.2733x over previous
#include <cuda_runtime.h>

// ROIAlign, torchvision semantics:
//   features: (N=2, C=256, H=200, W=304) fp32 NCHW
//   boxes:    (R=1000, 5) fp32 [batch_idx, x1, y1, x2, y2]
//   output:   (R, C, 7, 7) fp32
// spatial_scale = 0.25, sampling_ratio = 2, mean over 2x2 samples.
//
// Warp-per-plane layout: one warp handles one (box, channel) plane.
// Lane = (iy, pw, ix): 2 sample-rows x 7 bins x 2 x-samples = 28 active lanes.
// Each corner LDG then spans only ~2 feature rows x ~2 cache lines instead of
// ~5 rows x 2 lines x multiple planes -> ~4.5x fewer L1tex wavefronts.

namespace {

constexpr int   C_DIM = 256;
constexpr int   H_DIM = 200;
constexpr int   W_DIM = 304;
constexpr int   PH    = 7;
constexpr int   PW    = 7;
constexpr float SCALE = 0.25f;

__device__ __forceinline__ void axis_interp(float coord, int size,
                                            int& lo, int& hi,
                                            float& frac, bool& valid) {
    valid = (coord >= -1.0f) && (coord <= (float)size);
    float c = fmaxf(coord, 0.0f);
    int low = (int)c;                 // floor (c >= 0)
    if (low >= size - 1) {
        lo = size - 1; hi = size - 1; frac = 0.0f;
    } else {
        lo = low; hi = low + 1; frac = c - (float)low;
    }
}

__global__ __launch_bounds__(256)
void roi_align_warp_kernel(const float* __restrict__ feat,
                           const float* __restrict__ boxes,
                           float* __restrict__ out,
                           int num_planes) {
    int warp_id = (int)((blockIdx.x * blockDim.x + threadIdx.x) >> 5);
    int lane    = threadIdx.x & 31;
    if (warp_id >= num_planes) return;

    int r = warp_id / C_DIM;          // box index
    int c = warp_id % C_DIM;          // channel

    // Box params: lane-uniform loads (broadcast, single wavefront).
    const float* bx = boxes + (size_t)r * 5;
    int   b  = (int)__ldg(bx + 0);
    float x1 = __ldg(bx + 1) * SCALE;
    float y1 = __ldg(bx + 2) * SCALE;
    float x2 = __ldg(bx + 3) * SCALE;
    float y2 = __ldg(bx + 4) * SCALE;

    float bin_w = fmaxf(x2 - x1, 1.0f) * (1.0f / PW);
    float bin_h = fmaxf(y2 - y1, 1.0f) * (1.0f / PH);

    const float* fp = feat + ((size_t)b * C_DIM + c) * (H_DIM * W_DIM);

    // Lane decomposition: lanes 28..31 duplicate lane 27 (kept active so all
    // shuffles run with full mask; they never write).
    int l  = lane < 28 ? lane : 27;
    int iy = l / 14;                  // sample row within bin (0/1)
    int t  = l % 14;
    int pw = t >> 1;                  // output bin column
    int ix = t & 1;                   // sample col within bin (0/1)

    // X-axis interp params: identical for every ph -> hoisted out of loop.
    float x = x1 + ((float)pw + ((float)ix + 0.5f) * 0.5f) * bin_w;
    int xl, xh; float fx; bool vx;
    axis_interp(x, W_DIM, xl, xh, fx, vx);
    float gx = 1.0f - fx;

    size_t out_base = (size_t)warp_id * (PH * PW);
    bool writer = (lane < 14) && ((lane & 1) == 0);

#pragma unroll
    for (int ph = 0; ph < PH; ph++) {
        float y = y1 + ((float)ph + ((float)iy + 0.5f) * 0.5f) * bin_h;
        int yl, yh; float fy; bool vy;
        axis_interp(y, H_DIM, yl, yh, fy, vy);

        const float* rowl = fp + yl * W_DIM;
        const float* rowh = fp + yh * W_DIM;
        float vll = __ldg(rowl + xl);
        float vlh = __ldg(rowl + xh);
        float vhl = __ldg(rowh + xl);
        float vhh = __ldg(rowh + xh);

        float gy  = 1.0f - fy;
        float val = gy * (gx * vll + fx * vlh) + fy * (gx * vhl + fx * vhh);
        if (!(vx && vy)) val = 0.0f;

        // Reduce the 2x2 sample grid for each bin:
        //   lane ^ 1  : sums the ix pair (same iy, pw)
        //   lane + 14 : adds the iy=1 partner onto iy=0 lanes
        float s = val + __shfl_xor_sync(0xFFFFFFFFu, val, 1);
        s      += __shfl_down_sync(0xFFFFFFFFu, s, 14);

        if (writer)
            out[out_base + ph * PW + pw] = s * 0.25f;
    }
}

} // namespace

extern "C" void kernel_launch(void* const* d_in, const int* in_sizes, int n_in,
                              void* d_out, int out_size) {
    const float* features = (const float*)d_in[0];
    const float* boxes    = (const float*)d_in[1];
    float*       out      = (float*)d_out;

    int num_planes = out_size / (PH * PW);      // R * C = 256000 warps
    int threads = 256;                          // 8 warps per block
    long long total_threads = (long long)num_planes * 32;
    int blocks = (int)((total_threads + threads - 1) / threads);
    roi_align_warp_kernel<<<blocks, threads>>>(features, boxes, out, num_planes);
}

// round 5
// speedup vs baseline: 1.6325x; 1.2821x over previous
#include <cuda_runtime.h>

// ROIAlign, torchvision semantics:
//   features: (N=2, C=256, H=200, W=304) fp32 NCHW
//   boxes:    (R=1000, 5) fp32 [batch_idx, x1, y1, x2, y2]
//   output:   (R, C, 7, 7) fp32
// spatial_scale = 0.25, sampling_ratio = 2, mean over 2x2 samples.
//
// One warp = one box x 4-channel group. Lane = (iy, pw, ix): 2 sample rows x
// 7 bins x 2 x-samples = 28 active lanes (L1-friendly gather footprint).
// Coordinate math amortized over K=4 channels; channel-group-major warp
// ordering keeps a ~2 MB active feature working set resident in L2.

namespace {

constexpr int   C_DIM = 256;
constexpr int   H_DIM = 200;
constexpr int   W_DIM = 304;
constexpr int   PH    = 7;
constexpr int   PW    = 7;
constexpr int   K     = 4;       // channels per warp
constexpr float SCALE = 0.25f;

__device__ __forceinline__ void axis_interp(float coord, int size,
                                            int& lo, int& hi,
                                            float& frac, bool& valid) {
    valid = (coord >= -1.0f) && (coord <= (float)size);
    float c = fmaxf(coord, 0.0f);
    int low = (int)c;                 // floor (c >= 0)
    if (low >= size - 1) {
        lo = size - 1; hi = size - 1; frac = 0.0f;
    } else {
        lo = low; hi = low + 1; frac = c - (float)low;
    }
}

__global__ __launch_bounds__(256)
void roi_align_k4_kernel(const float* __restrict__ feat,
                         const float* __restrict__ boxes,
                         float* __restrict__ out,
                         int num_units, int R) {
    int unit = (int)((blockIdx.x * blockDim.x + threadIdx.x) >> 5);
    int lane = threadIdx.x & 31;
    if (unit >= num_units) return;

    // Channel-group-major: concurrent warps share the same K channel planes.
    int r  = unit % R;                // box (fast axis)
    int cg = unit / R;                // channel group (slow axis)
    int c0 = cg * K;

    const float* bx = boxes + (size_t)r * 5;
    int   b  = (int)__ldg(bx + 0);
    float x1 = __ldg(bx + 1) * SCALE;
    float y1 = __ldg(bx + 2) * SCALE;
    float x2 = __ldg(bx + 3) * SCALE;
    float y2 = __ldg(bx + 4) * SCALE;

    float bin_w = fmaxf(x2 - x1, 1.0f) * (1.0f / PW);
    float bin_h = fmaxf(y2 - y1, 1.0f) * (1.0f / PH);

    const float* fp[K];
#pragma unroll
    for (int k = 0; k < K; k++)
        fp[k] = feat + ((size_t)(b * C_DIM + c0 + k)) * (H_DIM * W_DIM);

    // Lane decomposition (lanes 28..31 mirror lane 27; never write).
    int l  = lane < 28 ? lane : 27;
    int iy = l / 14;                  // sample row within bin (0/1)
    int t  = l % 14;
    int pw = t >> 1;                  // output bin column
    int ix = t & 1;                   // sample col within bin (0/1)

    // X interp: identical for every ph -> hoisted. Invalid x -> zero weights
    // (removes per-channel validity selects from the inner loop).
    float x = x1 + ((float)pw + ((float)ix + 0.5f) * 0.5f) * bin_w;
    int xl, xh; float fx; bool vx;
    axis_interp(x, W_DIM, xl, xh, fx, vx);
    float gx = 1.0f - fx;
    if (!vx) { gx = 0.0f; fx = 0.0f; }

    size_t out_base = ((size_t)r * C_DIM + c0) * (PH * PW);
    bool writer = (lane < 14) && ((lane & 1) == 0);

#pragma unroll
    for (int ph = 0; ph < PH; ph++) {
        float y = y1 + ((float)ph + ((float)iy + 0.5f) * 0.5f) * bin_h;
        int yl, yh; float fy; bool vy;
        axis_interp(y, H_DIM, yl, yh, fy, vy);
        float gy = 1.0f - fy;
        if (!vy) { gy = 0.0f; fy = 0.0f; }

        int ol = yl * W_DIM;
        int oh = yh * W_DIM;
        int oll = ol + xl, olh = ol + xh;
        int ohl = oh + xl, ohh = oh + xh;

        // Gather all 16 corners first (independent loads -> high MLP).
        float vll[K], vlh[K], vhl[K], vhh[K];
#pragma unroll
        for (int k = 0; k < K; k++) {
            vll[k] = __ldg(fp[k] + oll);
            vlh[k] = __ldg(fp[k] + olh);
            vhl[k] = __ldg(fp[k] + ohl);
            vhh[k] = __ldg(fp[k] + ohh);
        }

#pragma unroll
        for (int k = 0; k < K; k++) {
            float val = gy * (gx * vll[k] + fx * vlh[k])
                      + fy * (gx * vhl[k] + fx * vhh[k]);
            // Reduce 2x2 sample grid: ix pair via xor-1, iy pair via down-14.
            float s = val + __shfl_xor_sync(0xFFFFFFFFu, val, 1);
            s      += __shfl_down_sync(0xFFFFFFFFu, s, 14);
            if (writer)
                out[out_base + k * (PH * PW) + ph * PW + pw] = s * 0.25f;
        }
    }
}

} // namespace

extern "C" void kernel_launch(void* const* d_in, const int* in_sizes, int n_in,
                              void* d_out, int out_size) {
    const float* features = (const float*)d_in[0];
    const float* boxes    = (const float*)d_in[1];
    float*       out      = (float*)d_out;

    int R = in_sizes[1] / 5;                         // 1000 boxes
    int num_units = (out_size / (PH * PW)) / K;      // R * C / K = 64000 warps
    int threads = 256;                               // 8 warps / block
    long long total_threads = (long long)num_units * 32;
    int blocks = (int)((total_threads + threads - 1) / threads);
    roi_align_k4_kernel<<<blocks, threads>>>(features, boxes, out,
                                             num_units, R);
}